// round 11
// baseline (speedup 1.0000x reference)
#include <cuda_runtime.h>
#include <math.h>

#define G_N   40000
#define P_N   5
#define ZD    32
#define FD    64
#define HD    32
#define UVN   256
#define UV2   (UVN*UVN)
#define CC    64

// -------- scratch (device globals) --------
__device__ float g_uvmap[HD * UV2];
__device__ float g_buf0[CC * UV2];
__device__ float g_buf1[CC * UV2];
__device__ float g_bias1[P_N * 128];
__device__ float g_bias2[P_N * 128];
__device__ int   g_cnt[P_N];
__device__ int   g_cursor[P_N];
__device__ int   g_poff[P_N + 1];
__device__ int   g_order[40960];
__device__ float g_stats[2 * CC];            // mean[64], invstd[64]
__device__ float g_ssum[2 * CC];             // sum/sumsq accumulators (zero at rest)
#define WT_OUT_SZ  (9 * 64 * 8)
__device__ float g_wTo[WT_OUT_SZ];

// packed MLP weights, B-fragment order [ks][ng][lane][2], tf32-rounded.
#define WPK_PART 75776
#define WPK_L1A  0
#define WPK_L1B  4096
#define WPK_L1C  20480
#define WPK_L2A  36864
#define WPK_L2B  43008
#define WPK_L2C  59392
__device__ float g_wpack[P_N * WPK_PART];

// packed conv weights, B-fragment order [chunk][tap][group8][lane32][2]:
// element (c,t,g,l,h) = w[co=8g+(l>>2)][ci=8c+(l&3)+4h][t], tf32-rounded.
#define CPK_IN   (4 * 9 * 512)          // conv_in: cin=32 -> 4 chunks
#define CPK_HID  (8 * 9 * 512)          // hidden: cin=64 -> 8 chunks
#define CPK_TOTAL (CPK_IN + 3 * CPK_HID)
__device__ float g_cwp[CPK_TOTAL];

__device__ __forceinline__ float lrelu(float x) { return x > 0.f ? x : 0.01f * x; }

__device__ __forceinline__ unsigned f2tf(float v) {
    unsigned u;
    asm("cvt.rna.tf32.f32 %0, %1;" : "=r"(u) : "f"(v));
    return u;
}
__device__ __forceinline__ float f2tff(float v) { return __uint_as_float(f2tf(v)); }

__device__ __forceinline__ void mma_tf32(float* c, const unsigned* a, const unsigned* b) {
    asm volatile(
        "mma.sync.aligned.m16n8k8.row.col.f32.tf32.tf32.f32 "
        "{%0,%1,%2,%3}, {%4,%5,%6,%7}, {%8,%9}, {%0,%1,%2,%3};"
        : "+f"(c[0]), "+f"(c[1]), "+f"(c[2]), "+f"(c[3])
        : "r"(a[0]), "r"(a[1]), "r"(a[2]), "r"(a[3]), "r"(b[0]), "r"(b[1]));
}

// ============================================================
// prep kernels
// ============================================================
// launch 1: clear uvmap + count parts (g_cnt zeroed by previous replay's convout)
__global__ void clearcount_kernel(const int* __restrict__ gs_part) {
    int i = blockIdx.x * blockDim.x + threadIdx.x;
    float4 z = make_float4(0.f, 0.f, 0.f, 0.f);
    if (i < HD * UV2 / 4) reinterpret_cast<float4*>(g_uvmap)[i] = z;
    if (i < G_N) atomicAdd(&g_cnt[gs_part[i]], 1);
}

// launch 2: blocks 0-4 bias fold; block 5 offsets; blocks 6+ MLP weight packing
__global__ void partbias_offsets_pack_kernel(
    const float* __restrict__ latent_f,
    const float* __restrict__ w1in, const float* __restrict__ b1in,
    const float* __restrict__ w2in, const float* __restrict__ b2in,
    const float* __restrict__ w1hid, const float* __restrict__ w2hid) {
    if (blockIdx.x < 5) {
        int p = blockIdx.x, n = threadIdx.x;
        float s1 = b1in[p * 128 + n];
        float s2 = b2in[p * 128 + n];
        for (int k = 0; k < FD; k++) {
            float f = latent_f[p * FD + k];
            s1 += f * w1in[(p * 96 + k) * 128 + n];
            s2 += f * w2in[(p * 110 + k) * 128 + n];
        }
        g_bias1[p * 128 + n] = s1;
        g_bias2[p * 128 + n] = s2;
    } else if (blockIdx.x == 5) {
        if (threadIdx.x == 0) {
            int off = 0;
            for (int p = 0; p < P_N; p++) {
                g_poff[p] = off;
                off += ((g_cnt[p] + 63) >> 6) << 6;
                g_cursor[p] = 0;
            }
            g_poff[P_N] = off;
        }
    } else {
        int idx = (blockIdx.x - 6) * 128 + threadIdx.x;
        if (idx < P_N * WPK_PART) {
            int p = idx / WPK_PART, r = idx - p * WPK_PART;
            const float* src; int Kreal, loc;
            if (r < WPK_L1B)      { src = w1in + (p * 96 + 64) * 128;            Kreal = 32;  loc = r; }
            else if (r < WPK_L1C) { src = w1hid + p * 32768;                     Kreal = 128; loc = r - WPK_L1B; }
            else if (r < WPK_L2A) { src = w1hid + p * 32768 + 16384;             Kreal = 128; loc = r - WPK_L1C; }
            else if (r < WPK_L2B) { src = w2in + (p * 110 + 64) * 128;           Kreal = 46;  loc = r - WPK_L2A; }
            else if (r < WPK_L2C) { src = w2hid + p * 32768;                     Kreal = 128; loc = r - WPK_L2B; }
            else                  { src = w2hid + p * 32768 + 16384;             Kreal = 128; loc = r - WPK_L2C; }
            int h = loc & 1, lane = (loc >> 1) & 31, ng = (loc >> 6) & 15, ks = loc >> 10;
            int tc = lane & 3, gid = lane >> 2;
            int row = ks * 8 + tc + 4 * h, col = ng * 8 + gid;
            g_wpack[idx] = (row < Kreal) ? f2tff(src[row * 128 + col]) : 0.f;
        }
    }
}

// launch 3
__global__ void scatter_kernel(const int* __restrict__ gs_part) {
    int g = blockIdx.x * blockDim.x + threadIdx.x;
    if (g < G_N) {
        int p = gs_part[g];
        int pos = g_poff[p] + atomicAdd(&g_cursor[p], 1);
        g_order[pos] = g;
    }
}

// launch 5: pack conv weights into B-fragment order (+ convout [tap][ci][co8])
__global__ void pack_conv_kernel(const float* __restrict__ cinw,
                                 const float* __restrict__ chw,
                                 const float* __restrict__ cow) {
    int idx = blockIdx.x * blockDim.x + threadIdx.x;
    if (idx < CPK_IN) {
        int loc = idx;
        int h = loc & 1, l32 = (loc >> 1) & 31, g = (loc >> 6) & 7;
        int t = (loc >> 9) % 9, c = loc / (9 * 512);
        int tc = l32 & 3, gid = l32 >> 2;
        int ci = c * 8 + tc + 4 * h, co = g * 8 + gid;
        g_cwp[idx] = f2tff(cinw[(co * 32 + ci) * 9 + t]);
    } else if (idx < CPK_TOTAL) {
        int r = idx - CPK_IN;
        int l = r / CPK_HID, loc = r % CPK_HID;
        int h = loc & 1, l32 = (loc >> 1) & 31, g = (loc >> 6) & 7;
        int t = (loc >> 9) % 9, c = loc / (9 * 512);
        int tc = l32 & 3, gid = l32 >> 2;
        int ci = c * 8 + tc + 4 * h, co = g * 8 + gid;
        g_cwp[idx] = f2tff(chw[l * 36864 + (co * 64 + ci) * 9 + t]);
    } else if (idx < CPK_TOTAL + WT_OUT_SZ) {
        int r = idx - CPK_TOTAL;
        int co = r & 7, t = r >> 3;         // t = tap*64 + ci
        int ci = t & 63, tap = t >> 6;
        g_wTo[r] = (co < 3) ? f2tff(cow[(co * 64 + ci) * 9 + tap]) : 0.f;
    }
}

// ============================================================
// MLP: tf32 tensor cores, B fragments from packed global (R10 exact).
// ============================================================
#define AST 72

__device__ __forceinline__ void layer_mma_g(const float* __restrict__ A,
                                            const float* __restrict__ Wp,
                                            const float* __restrict__ bias,
                                            int Ksteps, float* Out, int tid) {
    const int lane = tid & 31, warp = tid >> 5;
    const int mw = warp & 1, nw = warp >> 1;
    const int gid = lane >> 2, tc = lane & 3;

    float c[2][4][4];
#pragma unroll
    for (int j = 0; j < 4; j++) {
        int n0 = nw * 32 + j * 8;
        float b0 = bias[n0 + 2 * tc], b1 = bias[n0 + 2 * tc + 1];
#pragma unroll
        for (int i = 0; i < 2; i++) { c[i][j][0] = b0; c[i][j][1] = b1; c[i][j][2] = b0; c[i][j][3] = b1; }
    }

    const float2* Wl = reinterpret_cast<const float2*>(Wp) + (nw * 4) * 32 + lane;

#pragma unroll 2
    for (int ks = 0; ks < Ksteps; ks++) {
        unsigned a[2][4];
#pragma unroll
        for (int i = 0; i < 2; i++) {
            const int m0 = mw * 32 + 16 * i;
            const float* Ab = A + ks * 8 * AST + m0;
            a[i][0] = __float_as_uint(Ab[tc * AST + gid]);
            a[i][1] = __float_as_uint(Ab[tc * AST + gid + 8]);
            a[i][2] = __float_as_uint(Ab[(tc + 4) * AST + gid]);
            a[i][3] = __float_as_uint(Ab[(tc + 4) * AST + gid + 8]);
        }
#pragma unroll
        for (int j = 0; j < 4; j++) {
            float2 bv = __ldg(Wl + (ks * 16 + j) * 32);
            unsigned b[2] = {__float_as_uint(bv.x), __float_as_uint(bv.y)};
            mma_tf32(c[0][j], a[0], b);
            mma_tf32(c[1][j], a[1], b);
        }
    }

    __syncthreads();
#pragma unroll
    for (int i = 0; i < 2; i++) {
        const int m0 = mw * 32 + 16 * i;
#pragma unroll
        for (int j = 0; j < 4; j++) {
            const int n0 = nw * 32 + 8 * j + 2 * tc;
            Out[n0 * AST + m0 + gid]           = f2tff(lrelu(c[i][j][0]));
            Out[(n0 + 1) * AST + m0 + gid]     = f2tff(lrelu(c[i][j][1]));
            Out[n0 * AST + m0 + gid + 8]       = f2tff(lrelu(c[i][j][2]));
            Out[(n0 + 1) * AST + m0 + gid + 8] = f2tff(lrelu(c[i][j][3]));
        }
    }
    __syncthreads();
}

__global__ void __launch_bounds__(256, 3) mlp_kernel(
    const float* __restrict__ latent_z, const float* __restrict__ cano_xyz,
    const float* __restrict__ b1hid,
    const float* __restrict__ w1out, const float* __restrict__ b1out,
    const float* __restrict__ b2hid,
    const float* __restrict__ w2out, const float* __restrict__ b2out,
    const int* __restrict__ uv_idx) {
    extern __shared__ float sm[];
    float* Es = sm;                      // [48][72]
    float* H  = Es + 48 * AST;           // [128][72]
    int*   gidxs = reinterpret_cast<int*>(H + 128 * AST);
    int*   uvs   = gidxs + 64;

    const int tid = threadIdx.x;
    const int base = blockIdx.x * 64;
    if (base >= g_poff[P_N]) return;
    int p = 0;
    while (p < P_N - 1 && base >= g_poff[p + 1]) p++;
    const int seg0 = g_poff[p];
    const int cnt  = g_cnt[p];

    if (tid < 64) {
        int srow = base - seg0 + tid;
        int gi = (srow < cnt) ? g_order[base + tid] : -1;
        gidxs[tid] = gi;
        uvs[tid] = (gi >= 0) ? uv_idx[gi] : 0;
    }
    __syncthreads();

    for (int idx = tid; idx < 64 * ZD; idx += 256) {
        int g = idx >> 5, k = idx & 31;
        int gi = gidxs[g];
        Es[k * AST + g] = (gi >= 0) ? f2tff(latent_z[gi * ZD + k]) : 0.f;
    }
    for (int idx = tid; idx < 64 * 3; idx += 256) {
        int g = idx / 3, k = idx - g * 3;
        int gi = gidxs[g];
        Es[(32 + k) * AST + g] = (gi >= 0) ? f2tff(cano_xyz[gi * 3 + k]) : 0.f;
    }
    for (int idx = tid; idx < 2 * AST; idx += 256) Es[46 * AST + idx] = 0.f;
    __syncthreads();

    const float* WP = g_wpack + p * WPK_PART;

    // ---- MLP1 ----
    layer_mma_g(Es, WP + WPK_L1A, g_bias1 + p * 128,       4,  H, tid);
    layer_mma_g(H,  WP + WPK_L1B, b1hid + p * 256,         16, H, tid);
    layer_mma_g(H,  WP + WPK_L1C, b1hid + p * 256 + 128,   16, H, tid);

    // attrs (N=11) scalar -> Es rows 35..45
    {
        int g = tid & 63, nb = tid >> 6;
        const float* wo = w1out + p * 128 * 11;
        float s0 = 0.f, s1 = 0.f, s2 = 0.f;
        bool has2 = (nb + 8) < 11;
        for (int k = 0; k < 128; k++) {
            float a = H[k * AST + g];
            s0 += a * __ldg(&wo[k * 11 + nb]);
            s1 += a * __ldg(&wo[k * 11 + nb + 4]);
            if (has2) s2 += a * __ldg(&wo[k * 11 + nb + 8]);
        }
        Es[(35 + nb) * AST + g]     = f2tff(s0 + b1out[p * 11 + nb]);
        Es[(35 + nb + 4) * AST + g] = f2tff(s1 + b1out[p * 11 + nb + 4]);
        if (has2) Es[(35 + nb + 8) * AST + g] = f2tff(s2 + b1out[p * 11 + nb + 8]);
    }
    __syncthreads();

    // ---- MLP2 ----
    layer_mma_g(Es, WP + WPK_L2A, g_bias2 + p * 128,       6,  H, tid);
    layer_mma_g(H,  WP + WPK_L2B, b2hid + p * 256,         16, H, tid);
    layer_mma_g(H,  WP + WPK_L2C, b2hid + p * 256 + 128,   16, H, tid);

    // final N=32 + scatter
    {
        const int g0 = (tid & 15) * 4;
        const int n0 = (tid >> 4) * 2;
        const float* wo = w2out + p * 128 * 32;
        float c[4][2];
#pragma unroll
        for (int j = 0; j < 2; j++) {
            float b = b2out[p * 32 + n0 + j];
#pragma unroll
            for (int i = 0; i < 4; i++) c[i][j] = b;
        }
#pragma unroll 4
        for (int k = 0; k < 128; k++) {
            float4 a = *reinterpret_cast<const float4*>(H + k * AST + g0);
            float w0 = __ldg(&wo[k * 32 + n0]), w1 = __ldg(&wo[k * 32 + n0 + 1]);
            float av[4] = {a.x, a.y, a.z, a.w};
#pragma unroll
            for (int i = 0; i < 4; i++) { c[i][0] += av[i] * w0; c[i][1] += av[i] * w1; }
        }
#pragma unroll
        for (int i = 0; i < 4; i++) {
            int gi = gidxs[g0 + i];
            if (gi >= 0) {
                int uv = uvs[g0 + i];
                g_uvmap[(n0 + 0) * UV2 + uv] = c[i][0];
                g_uvmap[(n0 + 1) * UV2 + uv] = c[i][1];
            }
        }
    }
}

// ============================================================
// CNN: tf32 3x3 conv, 16x16 tile x 64 couts; B fragments from packed
// global (no weight smem). pre: 0 raw, 1 relu, 2 instnorm+relu.
// ============================================================
__global__ void __launch_bounds__(256) conv3x3_tf32_kernel(
    const float* __restrict__ in, int cin,
    const float* __restrict__ wp,       // packed B fragments [chunk][tap][g][lane][2]
    const float* __restrict__ bias,
    float* __restrict__ out, int pre, int do_stats) {
    __shared__ __align__(16) float ins2[18 * 18 * 8];      // [pixel][tc*2+h], ci=tc+4h

    const int tid  = threadIdx.x;
    const int lane = tid & 31, warp = tid >> 5;
    const int mw = warp & 3, nw = warp >> 2;
    const int gid = lane >> 2, tc = lane & 3;
    const int bx = blockIdx.x, by = blockIdx.y;

    // warp's packed-B base (float2 units): ((c*9+t)*8 + nw*4 + j)*32 + lane
    const float2* Wl = reinterpret_cast<const float2*>(wp) + (nw * 4) * 32 + lane;

    float c[4][4][4] = {};

    const int nchunk = cin >> 3;
    for (int cc8 = 0; cc8 < nchunk; cc8++) {
        const int cc = cc8 * 8;
        for (int idx = tid; idx < 2592; idx += 256) {
            int ci = idx / 324, rem = idx - ci * 324;
            int y = rem / 18, x = rem - y * 18;
            int gy = by * 16 + y - 1, gx = bx * 16 + x - 1;
            float v = 0.f;
            if ((unsigned)gy < 256u && (unsigned)gx < 256u) {
                v = in[(cc + ci) * UV2 + gy * 256 + gx];
                if (pre == 2) v = (v - g_stats[cc + ci]) * g_stats[64 + cc + ci];
                if (pre) v = fmaxf(v, 0.f);
            }
            ins2[(y * 18 + x) * 8 + (ci & 3) * 2 + (ci >> 2)] = f2tff(v);
        }
        __syncthreads();

#pragma unroll
        for (int tap = 0; tap < 9; ++tap) {
            const int ky = tap / 3, kx = tap - 3 * (tap / 3);
            const float2* wb = Wl + (cc8 * 9 + tap) * 256;
            unsigned b[4][2];
#pragma unroll
            for (int j = 0; j < 4; ++j) {
                float2 bv = __ldg(wb + j * 32);
                b[j][0] = __float_as_uint(bv.x);
                b[j][1] = __float_as_uint(bv.y);
            }
#pragma unroll
            for (int i = 0; i < 4; ++i) {
                const int pixbase = (4 * mw + i + ky) * 18 + kx;
                float2 a0 = *reinterpret_cast<const float2*>(ins2 + (pixbase + gid) * 8 + 2 * tc);
                float2 a1 = *reinterpret_cast<const float2*>(ins2 + (pixbase + gid + 8) * 8 + 2 * tc);
                unsigned a[4];
                a[0] = __float_as_uint(a0.x);
                a[1] = __float_as_uint(a1.x);
                a[2] = __float_as_uint(a0.y);
                a[3] = __float_as_uint(a1.y);
#pragma unroll
                for (int j = 0; j < 4; ++j) mma_tf32(c[i][j], a, b[j]);
            }
        }
        __syncthreads();
    }

#pragma unroll
    for (int j = 0; j < 4; ++j) {
        const int co = nw * 32 + j * 8 + 2 * tc;
        const float b0 = bias[co], b1 = bias[co + 1];
        float s0 = 0.f, q0 = 0.f, s1 = 0.f, q1 = 0.f;
#pragma unroll
        for (int i = 0; i < 4; ++i) {
            const int gy = by * 16 + 4 * mw + i;
            const int gx = bx * 16;
            float v0 = c[i][j][0] + b0;
            float v1 = c[i][j][1] + b1;
            float v2 = c[i][j][2] + b0;
            float v3 = c[i][j][3] + b1;
            out[co * UV2 + gy * 256 + gx + gid]           = v0;
            out[(co + 1) * UV2 + gy * 256 + gx + gid]     = v1;
            out[co * UV2 + gy * 256 + gx + gid + 8]       = v2;
            out[(co + 1) * UV2 + gy * 256 + gx + gid + 8] = v3;
            s0 += v0 + v2; q0 += v0 * v0 + v2 * v2;
            s1 += v1 + v3; q1 += v1 * v1 + v3 * v3;
        }
        if (do_stats) {
#pragma unroll
            for (int off = 4; off < 32; off <<= 1) {
                s0 += __shfl_xor_sync(0xffffffffu, s0, off);
                q0 += __shfl_xor_sync(0xffffffffu, q0, off);
                s1 += __shfl_xor_sync(0xffffffffu, s1, off);
                q1 += __shfl_xor_sync(0xffffffffu, q1, off);
            }
            if (gid == 0) {
                atomicAdd(&g_ssum[co], s0);
                atomicAdd(&g_ssum[64 + co], q0);
                atomicAdd(&g_ssum[co + 1], s1);
                atomicAdd(&g_ssum[64 + co + 1], q1);
            }
        }
    }
}

// finalize instance-norm stats, reset accumulators
__global__ void finalize_stats_kernel() {
    int c = threadIdx.x;
    float s = g_ssum[c], q = g_ssum[64 + c];
    float m = s * (1.f / UV2);
    float var = q * (1.f / UV2) - m * m;
    g_stats[c] = m;
    g_stats[64 + c] = rsqrtf(fmaxf(var, 0.f) + 1e-5f);
    g_ssum[c] = 0.f;
    g_ssum[64 + c] = 0.f;
}

// conv_out (tensor): 64 -> 3 (padded 8), input IN'd, sigmoid (R8 exact).
__global__ void __launch_bounds__(256) convout_tf32_kernel(
    const float* __restrict__ in,
    const float* __restrict__ bias,
    float* __restrict__ out) {
    __shared__ __align__(16) float ins2[18 * 18 * 8];
    __shared__ __align__(16) float wsmo[9 * 4 * 40];

    const int tid  = threadIdx.x;
    const int lane = tid & 31, warp = tid >> 5;
    const int gid = lane >> 2, tc = lane & 3;
    const int bx = blockIdx.x, by = blockIdx.y;

    float c[2][4] = {};

    for (int cc = 0; cc < CC; cc += 8) {
        for (int idx = tid; idx < 2592; idx += 256) {
            int ci = idx / 324, rem = idx - ci * 324;
            int y = rem / 18, x = rem - y * 18;
            int gy = by * 16 + y - 1, gx = bx * 16 + x - 1;
            float v = 0.f;
            if ((unsigned)gy < 256u && (unsigned)gx < 256u) {
                v = in[(cc + ci) * UV2 + gy * 256 + gx];
                v = (v - g_stats[cc + ci]) * g_stats[64 + cc + ci];
            }
            ins2[(y * 18 + x) * 8 + (ci & 3) * 2 + (ci >> 2)] = f2tff(v);
        }
        for (int idx = tid; idx < 576; idx += 256) {
            int co = idx & 7, t = idx >> 3;     // t = tap*8+ci
            int ci = t & 7, tap = t >> 3;
            wsmo[(tap * 4 + (ci & 3)) * 40 + 2 * co + (ci >> 2)] =
                g_wTo[(tap * 64 + cc + ci) * 8 + co];
        }
        __syncthreads();

#pragma unroll
        for (int tap = 0; tap < 9; ++tap) {
            const int ky = tap / 3, kx = tap - 3 * (tap / 3);
            float2 bv = *reinterpret_cast<const float2*>(wsmo + (tap * 4 + tc) * 40 + 2 * gid);
            unsigned b[2] = {__float_as_uint(bv.x), __float_as_uint(bv.y)};
#pragma unroll
            for (int i = 0; i < 2; ++i) {
                const int pixbase = (2 * warp + i + ky) * 18 + kx;
                float2 a0 = *reinterpret_cast<const float2*>(ins2 + (pixbase + gid) * 8 + 2 * tc);
                float2 a1 = *reinterpret_cast<const float2*>(ins2 + (pixbase + gid + 8) * 8 + 2 * tc);
                unsigned a[4];
                a[0] = __float_as_uint(a0.x);
                a[1] = __float_as_uint(a1.x);
                a[2] = __float_as_uint(a0.y);
                a[3] = __float_as_uint(a1.y);
                mma_tf32(c[i], a, b);
            }
        }
        __syncthreads();
    }

#pragma unroll
    for (int i = 0; i < 2; ++i) {
        const int gy = by * 16 + 2 * warp + i;
        const int gx = bx * 16;
        const int co = 2 * tc;
        if (co < 3) {
            float v0 = 1.f / (1.f + expf(-(c[i][0] + bias[co])));
            float v2 = 1.f / (1.f + expf(-(c[i][2] + bias[co])));
            out[co * UV2 + gy * 256 + gx + gid]     = v0;
            out[co * UV2 + gy * 256 + gx + gid + 8] = v2;
        }
        if (co + 1 < 3) {
            float v1 = 1.f / (1.f + expf(-(c[i][1] + bias[co + 1])));
            float v3 = 1.f / (1.f + expf(-(c[i][3] + bias[co + 1])));
            out[(co + 1) * UV2 + gy * 256 + gx + gid]     = v1;
            out[(co + 1) * UV2 + gy * 256 + gx + gid + 8] = v3;
        }
    }
    // reset part counters for next graph replay (last kernel in the graph)
    if (bx == 0 && by == 0 && tid < P_N) g_cnt[tid] = 0;
}

// ============================================================
// host launch
// ============================================================
#define MLP_SMEM ((48 * AST + 128 * AST) * 4 + 128 * 4 + 256)
#define WPK_TOTAL (P_N * WPK_PART)

extern "C" void kernel_launch(void* const* d_in, const int* in_sizes, int n_in,
                              void* d_out, int out_size) {
    const float* latent_z = (const float*)d_in[0];
    const float* latent_f = (const float*)d_in[1];
    const float* cano_xyz = (const float*)d_in[2];
    const float* w1in  = (const float*)d_in[3];
    const float* b1in  = (const float*)d_in[4];
    const float* w1hid = (const float*)d_in[5];
    const float* b1hid = (const float*)d_in[6];
    const float* w1out = (const float*)d_in[7];
    const float* b1out = (const float*)d_in[8];
    const float* w2in  = (const float*)d_in[9];
    const float* b2in  = (const float*)d_in[10];
    const float* w2hid = (const float*)d_in[11];
    const float* b2hid = (const float*)d_in[12];
    const float* w2out = (const float*)d_in[13];
    const float* b2out = (const float*)d_in[14];
    const float* cinw  = (const float*)d_in[15];
    const float* cinb  = (const float*)d_in[16];
    const float* chw   = (const float*)d_in[17];
    const float* chb   = (const float*)d_in[18];
    const float* cow   = (const float*)d_in[19];
    const float* cobb  = (const float*)d_in[20];
    const int* gs_part = (const int*)d_in[21];
    const int* uv_idx  = (const int*)d_in[22];
    float* out = (float*)d_out;

    cudaFuncSetAttribute(mlp_kernel, cudaFuncAttributeMaxDynamicSharedMemorySize, MLP_SMEM);

    float *uvmap, *buf0, *buf1, *cwp;
    cudaGetSymbolAddress((void**)&uvmap, g_uvmap);
    cudaGetSymbolAddress((void**)&buf0, g_buf0);
    cudaGetSymbolAddress((void**)&buf1, g_buf1);
    cudaGetSymbolAddress((void**)&cwp, g_cwp);

    clearcount_kernel<<<2048, 256>>>(gs_part);                                 // 1
    partbias_offsets_pack_kernel<<<6 + (WPK_TOTAL + 127) / 128, 128>>>(        // 2
        latent_f, w1in, b1in, w2in, b2in, w1hid, w2hid);
    scatter_kernel<<<(G_N + 255) / 256, 256>>>(gs_part);                       // 3
    mlp_kernel<<<G_N / 64 + P_N, 256, MLP_SMEM>>>(latent_z, cano_xyz,          // 4 (capture)
        b1hid, w1out, b1out, b2hid, w2out, b2out, uv_idx);

    pack_conv_kernel<<<(CPK_TOTAL + WT_OUT_SZ + 255) / 256, 256>>>(cinw, chw, cow); // 5

    dim3 cgrid(UVN / 16, UVN / 16);
    conv3x3_tf32_kernel<<<cgrid, 256>>>(uvmap, HD, cwp, cinb, buf0, 0, 0);
    conv3x3_tf32_kernel<<<cgrid, 256>>>(buf0, CC, cwp + CPK_IN, chb, buf1, 1, 1);
    finalize_stats_kernel<<<1, 64>>>();
    conv3x3_tf32_kernel<<<cgrid, 256>>>(buf1, CC, cwp + CPK_IN + CPK_HID, chb + CC, buf0, 2, 1);
    finalize_stats_kernel<<<1, 64>>>();
    conv3x3_tf32_kernel<<<cgrid, 256>>>(buf0, CC, cwp + CPK_IN + 2 * CPK_HID, chb + 2 * CC, buf1, 2, 1);
    finalize_stats_kernel<<<1, 64>>>();
    convout_tf32_kernel<<<cgrid, 256>>>(buf1, cobb, out);
}

// round 12
// speedup vs baseline: 1.0860x; 1.0860x over previous
#include <cuda_runtime.h>
#include <math.h>

#define G_N   40000
#define P_N   5
#define ZD    32
#define FD    64
#define HD    32
#define UVN   256
#define UV2   (UVN*UVN)
#define CC    64

// -------- scratch (device globals) --------
__device__ float g_uvmap[HD * UV2];
__device__ float g_buf0[CC * UV2];
__device__ float g_buf1[CC * UV2];
__device__ float g_bias1[P_N * 128];
__device__ float g_bias2[P_N * 128];
__device__ int   g_cnt[P_N];
__device__ int   g_cursor[P_N];
__device__ int   g_poff[P_N + 1];
__device__ int   g_order[40960];
__device__ float g_stats[2 * CC];            // mean[64], invstd[64]
__device__ float g_ssum[2 * CC];             // sum/sumsq accumulators (zero at rest)
#define WT_IN_SZ   (9 * 32 * 64)
#define WT_HID_SZ  (9 * 64 * 64)
#define WT_OUT_SZ  (9 * 64 * 8)
__device__ float g_wT[WT_IN_SZ + 3 * WT_HID_SZ];
__device__ float g_wTo[WT_OUT_SZ];

// packed MLP weights, B-fragment order [ks][ng][lane][2], tf32-rounded.
// per part: L1a | L1b | L1c | L2a | L2b | L2c | O1 (N16) | O2 (N32)
#define WPK_PART 81920
#define WPK_L1A  0
#define WPK_L1B  4096
#define WPK_L1C  20480
#define WPK_L2A  36864
#define WPK_L2B  43008
#define WPK_L2C  59392
#define WPK_O1   75776
#define WPK_O2   77824
__device__ float g_wpack[P_N * WPK_PART];

__device__ __forceinline__ float lrelu(float x) { return x > 0.f ? x : 0.01f * x; }

__device__ __forceinline__ unsigned f2tf(float v) {
    unsigned u;
    asm("cvt.rna.tf32.f32 %0, %1;" : "=r"(u) : "f"(v));
    return u;
}
__device__ __forceinline__ float f2tff(float v) { return __uint_as_float(f2tf(v)); }

__device__ __forceinline__ void mma_tf32(float* c, const unsigned* a, const unsigned* b) {
    asm volatile(
        "mma.sync.aligned.m16n8k8.row.col.f32.tf32.tf32.f32 "
        "{%0,%1,%2,%3}, {%4,%5,%6,%7}, {%8,%9}, {%0,%1,%2,%3};"
        : "+f"(c[0]), "+f"(c[1]), "+f"(c[2]), "+f"(c[3])
        : "r"(a[0]), "r"(a[1]), "r"(a[2]), "r"(a[3]), "r"(b[0]), "r"(b[1]));
}

// ============================================================
// prep kernels
// ============================================================
// launch 1: clear uvmap + count parts (g_cnt zeroed by previous replay's convout)
__global__ void clearcount_kernel(const int* __restrict__ gs_part) {
    int i = blockIdx.x * blockDim.x + threadIdx.x;
    float4 z = make_float4(0.f, 0.f, 0.f, 0.f);
    if (i < HD * UV2 / 4) reinterpret_cast<float4*>(g_uvmap)[i] = z;
    if (i < G_N) atomicAdd(&g_cnt[gs_part[i]], 1);
}

// launch 2: blocks 0-4 bias fold; block 5 offsets; blocks 6+ MLP weight packing
__global__ void partbias_offsets_pack_kernel(
    const float* __restrict__ latent_f,
    const float* __restrict__ w1in, const float* __restrict__ b1in,
    const float* __restrict__ w2in, const float* __restrict__ b2in,
    const float* __restrict__ w1hid, const float* __restrict__ w2hid,
    const float* __restrict__ w1out, const float* __restrict__ w2out) {
    if (blockIdx.x < 5) {
        int p = blockIdx.x, n = threadIdx.x;
        float s1 = b1in[p * 128 + n];
        float s2 = b2in[p * 128 + n];
        for (int k = 0; k < FD; k++) {
            float f = latent_f[p * FD + k];
            s1 += f * w1in[(p * 96 + k) * 128 + n];
            s2 += f * w2in[(p * 110 + k) * 128 + n];
        }
        g_bias1[p * 128 + n] = s1;
        g_bias2[p * 128 + n] = s2;
    } else if (blockIdx.x == 5) {
        if (threadIdx.x == 0) {
            int off = 0;
            for (int p = 0; p < P_N; p++) {
                g_poff[p] = off;
                off += ((g_cnt[p] + 63) >> 6) << 6;
                g_cursor[p] = 0;
            }
            g_poff[P_N] = off;
        }
    } else {
        int idx = (blockIdx.x - 6) * 128 + threadIdx.x;
        if (idx < P_N * WPK_PART) {
            int p = idx / WPK_PART, r = idx - p * WPK_PART;
            float val;
            if (r < WPK_O1) {
                // 128-wide layers: [ks][ng16][lane][2]
                const float* src; int Kreal, loc;
                if (r < WPK_L1B)      { src = w1in + (p * 96 + 64) * 128;   Kreal = 32;  loc = r; }
                else if (r < WPK_L1C) { src = w1hid + p * 32768;            Kreal = 128; loc = r - WPK_L1B; }
                else if (r < WPK_L2A) { src = w1hid + p * 32768 + 16384;    Kreal = 128; loc = r - WPK_L1C; }
                else if (r < WPK_L2B) { src = w2in + (p * 110 + 64) * 128;  Kreal = 46;  loc = r - WPK_L2A; }
                else if (r < WPK_L2C) { src = w2hid + p * 32768;            Kreal = 128; loc = r - WPK_L2B; }
                else                  { src = w2hid + p * 32768 + 16384;    Kreal = 128; loc = r - WPK_L2C; }
                int h = loc & 1, lane = (loc >> 1) & 31, ng = (loc >> 6) & 15, ks = loc >> 10;
                int tc = lane & 3, gid = lane >> 2;
                int row = ks * 8 + tc + 4 * h, col = ng * 8 + gid;
                val = (row < Kreal) ? f2tff(src[row * 128 + col]) : 0.f;
            } else if (r < WPK_O2) {
                // w1out: N=16 (11 real), K=128
                int loc = r - WPK_O1;
                int h = loc & 1, lane = (loc >> 1) & 31, ng = (loc >> 6) & 1, ks = loc >> 7;
                int tc = lane & 3, gid = lane >> 2;
                int row = ks * 8 + tc + 4 * h, col = ng * 8 + gid;
                val = (col < 11) ? f2tff(w1out[p * 1408 + row * 11 + col]) : 0.f;
            } else {
                // w2out: N=32, K=128
                int loc = r - WPK_O2;
                int h = loc & 1, lane = (loc >> 1) & 31, ng = (loc >> 6) & 3, ks = loc >> 8;
                int tc = lane & 3, gid = lane >> 2;
                int row = ks * 8 + tc + 4 * h, col = ng * 8 + gid;
                val = f2tff(w2out[p * 4096 + row * 32 + col]);
            }
            g_wpack[idx] = val;
        }
    }
}

// launch 3
__global__ void scatter_kernel(const int* __restrict__ gs_part) {
    int g = blockIdx.x * blockDim.x + threadIdx.x;
    if (g < G_N) {
        int p = gs_part[g];
        int pos = g_poff[p] + atomicAdd(&g_cursor[p], 1);
        g_order[pos] = g;
    }
}

// launch 5: transpose conv weights [co][ci][tap] -> [tap][ci][co], tf32 (R10)
__global__ void transpose_w_kernel(const float* __restrict__ cinw,
                                   const float* __restrict__ chw,
                                   const float* __restrict__ cow) {
    int idx = blockIdx.x * blockDim.x + threadIdx.x;
    if (idx < WT_IN_SZ) {
        int co = idx & 63, t = idx >> 6;
        int ci = t % 32, tap = t / 32;
        g_wT[idx] = f2tff(cinw[(co * 32 + ci) * 9 + tap]);
    } else if (idx < WT_IN_SZ + 3 * WT_HID_SZ) {
        int r = idx - WT_IN_SZ;
        int l = r / WT_HID_SZ, i = r % WT_HID_SZ;
        int co = i & 63, t = i >> 6;
        int ci = t & 63, tap = t >> 6;
        g_wT[idx] = f2tff(chw[l * 64 * 64 * 9 + (co * 64 + ci) * 9 + tap]);
    } else if (idx < WT_IN_SZ + 3 * WT_HID_SZ + WT_OUT_SZ) {
        int r = idx - WT_IN_SZ - 3 * WT_HID_SZ;
        int co = r & 7, t = r >> 3;         // t = tap*64 + ci
        int ci = t & 63, tap = t >> 6;
        g_wTo[r] = (co < 3) ? f2tff(cow[(co * 64 + ci) * 9 + tap]) : 0.f;
    }
}

// ============================================================
// MLP: all-tensor tf32; B fragments from packed global.
// ============================================================
#define AST 72

__device__ __forceinline__ void layer_mma_g(const float* __restrict__ A,
                                            const float* __restrict__ Wp,
                                            const float* __restrict__ bias,
                                            int Ksteps, float* Out, int tid) {
    const int lane = tid & 31, warp = tid >> 5;
    const int mw = warp & 1, nw = warp >> 1;
    const int gid = lane >> 2, tc = lane & 3;

    float c[2][4][4];
#pragma unroll
    for (int j = 0; j < 4; j++) {
        int n0 = nw * 32 + j * 8;
        float b0 = bias[n0 + 2 * tc], b1 = bias[n0 + 2 * tc + 1];
#pragma unroll
        for (int i = 0; i < 2; i++) { c[i][j][0] = b0; c[i][j][1] = b1; c[i][j][2] = b0; c[i][j][3] = b1; }
    }

    const float2* Wl = reinterpret_cast<const float2*>(Wp) + (nw * 4) * 32 + lane;

#pragma unroll 2
    for (int ks = 0; ks < Ksteps; ks++) {
        unsigned a[2][4];
#pragma unroll
        for (int i = 0; i < 2; i++) {
            const int m0 = mw * 32 + 16 * i;
            const float* Ab = A + ks * 8 * AST + m0;
            a[i][0] = __float_as_uint(Ab[tc * AST + gid]);
            a[i][1] = __float_as_uint(Ab[tc * AST + gid + 8]);
            a[i][2] = __float_as_uint(Ab[(tc + 4) * AST + gid]);
            a[i][3] = __float_as_uint(Ab[(tc + 4) * AST + gid + 8]);
        }
#pragma unroll
        for (int j = 0; j < 4; j++) {
            float2 bv = __ldg(Wl + (ks * 16 + j) * 32);
            unsigned b[2] = {__float_as_uint(bv.x), __float_as_uint(bv.y)};
            mma_tf32(c[0][j], a[0], b);
            mma_tf32(c[1][j], a[1], b);
        }
    }

    __syncthreads();
#pragma unroll
    for (int i = 0; i < 2; i++) {
        const int m0 = mw * 32 + 16 * i;
#pragma unroll
        for (int j = 0; j < 4; j++) {
            const int n0 = nw * 32 + 8 * j + 2 * tc;
            Out[n0 * AST + m0 + gid]           = f2tff(lrelu(c[i][j][0]));
            Out[(n0 + 1) * AST + m0 + gid]     = f2tff(lrelu(c[i][j][1]));
            Out[n0 * AST + m0 + gid + 8]       = f2tff(lrelu(c[i][j][2]));
            Out[(n0 + 1) * AST + m0 + gid + 8] = f2tff(lrelu(c[i][j][3]));
        }
    }
    __syncthreads();
}

__global__ void __launch_bounds__(256, 3) mlp_kernel(
    const float* __restrict__ latent_z, const float* __restrict__ cano_xyz,
    const float* __restrict__ b1hid, const float* __restrict__ b1out,
    const float* __restrict__ b2hid, const float* __restrict__ b2out,
    const int* __restrict__ uv_idx) {
    extern __shared__ float sm[];
    float* Es = sm;                      // [48][72]
    float* H  = Es + 48 * AST;           // [128][72]
    int*   gidxs = reinterpret_cast<int*>(H + 128 * AST);
    int*   uvs   = gidxs + 64;

    const int tid = threadIdx.x;
    const int lane = tid & 31, warp = tid >> 5;
    const int gid = lane >> 2, tc = lane & 3;
    const int base = blockIdx.x * 64;
    if (base >= g_poff[P_N]) return;
    int p = 0;
    while (p < P_N - 1 && base >= g_poff[p + 1]) p++;
    const int seg0 = g_poff[p];
    const int cnt  = g_cnt[p];

    if (tid < 64) {
        int srow = base - seg0 + tid;
        int gi = (srow < cnt) ? g_order[base + tid] : -1;
        gidxs[tid] = gi;
        uvs[tid] = (gi >= 0) ? uv_idx[gi] : 0;
    }
    __syncthreads();

    for (int idx = tid; idx < 64 * ZD; idx += 256) {
        int g = idx >> 5, k = idx & 31;
        int gi = gidxs[g];
        Es[k * AST + g] = (gi >= 0) ? f2tff(latent_z[gi * ZD + k]) : 0.f;
    }
    for (int idx = tid; idx < 64 * 3; idx += 256) {
        int g = idx / 3, k = idx - g * 3;
        int gi = gidxs[g];
        Es[(32 + k) * AST + g] = (gi >= 0) ? f2tff(cano_xyz[gi * 3 + k]) : 0.f;
    }
    for (int idx = tid; idx < 2 * AST; idx += 256) Es[46 * AST + idx] = 0.f;
    __syncthreads();

    const float* WP = g_wpack + p * WPK_PART;

    // ---- MLP1 ----
    layer_mma_g(Es, WP + WPK_L1A, g_bias1 + p * 128,       4,  H, tid);
    layer_mma_g(H,  WP + WPK_L1B, b1hid + p * 256,         16, H, tid);
    layer_mma_g(H,  WP + WPK_L1C, b1hid + p * 256 + 128,   16, H, tid);

    // ---- attrs via mma: N=16 (11 real) -> Es rows 35..45 ----
    {
        const int mt = warp & 3, nt = warp >> 2;   // 4 M-tiles x 2 N-tiles
        float co[4] = {0.f, 0.f, 0.f, 0.f};
        const float2* Wl = reinterpret_cast<const float2*>(WP + WPK_O1) + lane;
#pragma unroll 2
        for (int ks = 0; ks < 16; ks++) {
            const float* Ab = H + ks * 8 * AST + mt * 16;
            unsigned a[4];
            a[0] = __float_as_uint(Ab[tc * AST + gid]);
            a[1] = __float_as_uint(Ab[tc * AST + gid + 8]);
            a[2] = __float_as_uint(Ab[(tc + 4) * AST + gid]);
            a[3] = __float_as_uint(Ab[(tc + 4) * AST + gid + 8]);
            float2 bv = __ldg(Wl + (ks * 2 + nt) * 32);
            unsigned b[2] = {__float_as_uint(bv.x), __float_as_uint(bv.y)};
            mma_tf32(co, a, b);
        }
        const int n0 = nt * 8 + 2 * tc;
        const int m  = mt * 16 + gid;
        if (n0 < 11) {
            float bb = b1out[p * 11 + n0];
            Es[(35 + n0) * AST + m]     = f2tff(co[0] + bb);
            Es[(35 + n0) * AST + m + 8] = f2tff(co[2] + bb);
        }
        if (n0 + 1 < 11) {
            float bb = b1out[p * 11 + n0 + 1];
            Es[(35 + n0 + 1) * AST + m]     = f2tff(co[1] + bb);
            Es[(35 + n0 + 1) * AST + m + 8] = f2tff(co[3] + bb);
        }
    }
    __syncthreads();

    // ---- MLP2 ----
    layer_mma_g(Es, WP + WPK_L2A, g_bias2 + p * 128,       6,  H, tid);
    layer_mma_g(H,  WP + WPK_L2B, b2hid + p * 256,         16, H, tid);
    layer_mma_g(H,  WP + WPK_L2C, b2hid + p * 256 + 128,   16, H, tid);

    // ---- final via mma: N=32, scatter to uvmap ----
    {
        const int mt = warp & 3, np = warp >> 2;   // 4 M-tiles x 2 N-tile-pairs
        float co[2][4] = {};
        const float2* Wl = reinterpret_cast<const float2*>(WP + WPK_O2) + lane;
#pragma unroll 2
        for (int ks = 0; ks < 16; ks++) {
            const float* Ab = H + ks * 8 * AST + mt * 16;
            unsigned a[4];
            a[0] = __float_as_uint(Ab[tc * AST + gid]);
            a[1] = __float_as_uint(Ab[tc * AST + gid + 8]);
            a[2] = __float_as_uint(Ab[(tc + 4) * AST + gid]);
            a[3] = __float_as_uint(Ab[(tc + 4) * AST + gid + 8]);
#pragma unroll
            for (int jj = 0; jj < 2; jj++) {
                float2 bv = __ldg(Wl + (ks * 4 + 2 * np + jj) * 32);
                unsigned b[2] = {__float_as_uint(bv.x), __float_as_uint(bv.y)};
                mma_tf32(co[jj], a, b);
            }
        }
        const int m = mt * 16 + gid;
        const int gi0 = gidxs[m], gi1 = gidxs[m + 8];
        const int uv0 = uvs[m],   uv1 = uvs[m + 8];
#pragma unroll
        for (int jj = 0; jj < 2; jj++) {
            const int n0 = (2 * np + jj) * 8 + 2 * tc;
            const float b0 = b2out[p * 32 + n0], b1 = b2out[p * 32 + n0 + 1];
            if (gi0 >= 0) {
                g_uvmap[n0 * UV2 + uv0]       = co[jj][0] + b0;
                g_uvmap[(n0 + 1) * UV2 + uv0] = co[jj][1] + b1;
            }
            if (gi1 >= 0) {
                g_uvmap[n0 * UV2 + uv1]       = co[jj][2] + b0;
                g_uvmap[(n0 + 1) * UV2 + uv1] = co[jj][3] + b1;
            }
        }
    }
}

// ============================================================
// CNN: tf32 3x3 conv, 16x16 tile x 64 couts, smem weights (R10 exact).
// ============================================================
#define WST 136
__global__ void __launch_bounds__(256) conv3x3_tf32_kernel(
    const float* __restrict__ in, int cin,
    const float* __restrict__ wT,
    const float* __restrict__ bias,
    float* __restrict__ out, int pre, int do_stats) {
    __shared__ __align__(16) float ins2[18 * 18 * 8];      // [pixel][tc*2+h], ci=tc+4h
    __shared__ __align__(16) float wsm2[9 * 4 * WST];      // [(tap*4+tc)][2co+h]

    const int tid  = threadIdx.x;
    const int lane = tid & 31, warp = tid >> 5;
    const int mw = warp & 3, nw = warp >> 2;
    const int gid = lane >> 2, tc = lane & 3;
    const int bx = blockIdx.x, by = blockIdx.y;

    float c[4][4][4] = {};

    for (int cc = 0; cc < cin; cc += 8) {
        for (int idx = tid; idx < 2592; idx += 256) {
            int ci = idx / 324, rem = idx - ci * 324;
            int y = rem / 18, x = rem - y * 18;
            int gy = by * 16 + y - 1, gx = bx * 16 + x - 1;
            float v = 0.f;
            if ((unsigned)gy < 256u && (unsigned)gx < 256u) {
                v = in[(cc + ci) * UV2 + gy * 256 + gx];
                if (pre == 2) v = (v - g_stats[cc + ci]) * g_stats[64 + cc + ci];
                if (pre) v = fmaxf(v, 0.f);
            }
            ins2[(y * 18 + x) * 8 + (ci & 3) * 2 + (ci >> 2)] = f2tff(v);
        }
        for (int idx = tid; idx < 4608; idx += 256) {
            int co = idx & 63, t = idx >> 6;      // t = tap*8+ci
            int ci = t & 7, tap = t >> 3;
            wsm2[(tap * 4 + (ci & 3)) * WST + 2 * co + (ci >> 2)] =
                wT[(tap * cin + cc + ci) * 64 + co];
        }
        __syncthreads();

#pragma unroll
        for (int tap = 0; tap < 9; ++tap) {
            const int ky = tap / 3, kx = tap - 3 * (tap / 3);
            unsigned b[4][2];
            {
                const float* wr = wsm2 + (tap * 4 + tc) * WST;
#pragma unroll
                for (int j = 0; j < 4; ++j) {
                    int n = nw * 32 + j * 8 + gid;
                    float2 bv = *reinterpret_cast<const float2*>(wr + 2 * n);
                    b[j][0] = __float_as_uint(bv.x);
                    b[j][1] = __float_as_uint(bv.y);
                }
            }
#pragma unroll
            for (int i = 0; i < 4; ++i) {
                const int pixbase = (4 * mw + i + ky) * 18 + kx;
                float2 a0 = *reinterpret_cast<const float2*>(ins2 + (pixbase + gid) * 8 + 2 * tc);
                float2 a1 = *reinterpret_cast<const float2*>(ins2 + (pixbase + gid + 8) * 8 + 2 * tc);
                unsigned a[4];
                a[0] = __float_as_uint(a0.x);
                a[1] = __float_as_uint(a1.x);
                a[2] = __float_as_uint(a0.y);
                a[3] = __float_as_uint(a1.y);
#pragma unroll
                for (int j = 0; j < 4; ++j) mma_tf32(c[i][j], a, b[j]);
            }
        }
        __syncthreads();
    }

#pragma unroll
    for (int j = 0; j < 4; ++j) {
        const int co = nw * 32 + j * 8 + 2 * tc;
        const float b0 = bias[co], b1 = bias[co + 1];
        float s0 = 0.f, q0 = 0.f, s1 = 0.f, q1 = 0.f;
#pragma unroll
        for (int i = 0; i < 4; ++i) {
            const int gy = by * 16 + 4 * mw + i;
            const int gx = bx * 16;
            float v0 = c[i][j][0] + b0;
            float v1 = c[i][j][1] + b1;
            float v2 = c[i][j][2] + b0;
            float v3 = c[i][j][3] + b1;
            out[co * UV2 + gy * 256 + gx + gid]           = v0;
            out[(co + 1) * UV2 + gy * 256 + gx + gid]     = v1;
            out[co * UV2 + gy * 256 + gx + gid + 8]       = v2;
            out[(co + 1) * UV2 + gy * 256 + gx + gid + 8] = v3;
            s0 += v0 + v2; q0 += v0 * v0 + v2 * v2;
            s1 += v1 + v3; q1 += v1 * v1 + v3 * v3;
        }
        if (do_stats) {
#pragma unroll
            for (int off = 4; off < 32; off <<= 1) {
                s0 += __shfl_xor_sync(0xffffffffu, s0, off);
                q0 += __shfl_xor_sync(0xffffffffu, q0, off);
                s1 += __shfl_xor_sync(0xffffffffu, s1, off);
                q1 += __shfl_xor_sync(0xffffffffu, q1, off);
            }
            if (gid == 0) {
                atomicAdd(&g_ssum[co], s0);
                atomicAdd(&g_ssum[64 + co], q0);
                atomicAdd(&g_ssum[co + 1], s1);
                atomicAdd(&g_ssum[64 + co + 1], q1);
            }
        }
    }
}

// finalize instance-norm stats, reset accumulators
__global__ void finalize_stats_kernel() {
    int c = threadIdx.x;
    float s = g_ssum[c], q = g_ssum[64 + c];
    float m = s * (1.f / UV2);
    float var = q * (1.f / UV2) - m * m;
    g_stats[c] = m;
    g_stats[64 + c] = rsqrtf(fmaxf(var, 0.f) + 1e-5f);
    g_ssum[c] = 0.f;
    g_ssum[64 + c] = 0.f;
}

// conv_out (tensor): 64 -> 3 (padded 8), input IN'd, sigmoid (R8 exact).
__global__ void __launch_bounds__(256) convout_tf32_kernel(
    const float* __restrict__ in,
    const float* __restrict__ bias,
    float* __restrict__ out) {
    __shared__ __align__(16) float ins2[18 * 18 * 8];
    __shared__ __align__(16) float wsmo[9 * 4 * 40];

    const int tid  = threadIdx.x;
    const int lane = tid & 31, warp = tid >> 5;
    const int gid = lane >> 2, tc = lane & 3;
    const int bx = blockIdx.x, by = blockIdx.y;

    float c[2][4] = {};

    for (int cc = 0; cc < CC; cc += 8) {
        for (int idx = tid; idx < 2592; idx += 256) {
            int ci = idx / 324, rem = idx - ci * 324;
            int y = rem / 18, x = rem - y * 18;
            int gy = by * 16 + y - 1, gx = bx * 16 + x - 1;
            float v = 0.f;
            if ((unsigned)gy < 256u && (unsigned)gx < 256u) {
                v = in[(cc + ci) * UV2 + gy * 256 + gx];
                v = (v - g_stats[cc + ci]) * g_stats[64 + cc + ci];
            }
            ins2[(y * 18 + x) * 8 + (ci & 3) * 2 + (ci >> 2)] = f2tff(v);
        }
        for (int idx = tid; idx < 576; idx += 256) {
            int co = idx & 7, t = idx >> 3;     // t = tap*8+ci
            int ci = t & 7, tap = t >> 3;
            wsmo[(tap * 4 + (ci & 3)) * 40 + 2 * co + (ci >> 2)] =
                g_wTo[(tap * 64 + cc + ci) * 8 + co];
        }
        __syncthreads();

#pragma unroll
        for (int tap = 0; tap < 9; ++tap) {
            const int ky = tap / 3, kx = tap - 3 * (tap / 3);
            float2 bv = *reinterpret_cast<const float2*>(wsmo + (tap * 4 + tc) * 40 + 2 * gid);
            unsigned b[2] = {__float_as_uint(bv.x), __float_as_uint(bv.y)};
#pragma unroll
            for (int i = 0; i < 2; ++i) {
                const int pixbase = (2 * warp + i + ky) * 18 + kx;
                float2 a0 = *reinterpret_cast<const float2*>(ins2 + (pixbase + gid) * 8 + 2 * tc);
                float2 a1 = *reinterpret_cast<const float2*>(ins2 + (pixbase + gid + 8) * 8 + 2 * tc);
                unsigned a[4];
                a[0] = __float_as_uint(a0.x);
                a[1] = __float_as_uint(a1.x);
                a[2] = __float_as_uint(a0.y);
                a[3] = __float_as_uint(a1.y);
                mma_tf32(c[i], a, b);
            }
        }
        __syncthreads();
    }

#pragma unroll
    for (int i = 0; i < 2; ++i) {
        const int gy = by * 16 + 2 * warp + i;
        const int gx = bx * 16;
        const int co = 2 * tc;
        if (co < 3) {
            float v0 = 1.f / (1.f + expf(-(c[i][0] + bias[co])));
            float v2 = 1.f / (1.f + expf(-(c[i][2] + bias[co])));
            out[co * UV2 + gy * 256 + gx + gid]     = v0;
            out[co * UV2 + gy * 256 + gx + gid + 8] = v2;
        }
        if (co + 1 < 3) {
            float v1 = 1.f / (1.f + expf(-(c[i][1] + bias[co + 1])));
            float v3 = 1.f / (1.f + expf(-(c[i][3] + bias[co + 1])));
            out[(co + 1) * UV2 + gy * 256 + gx + gid]     = v1;
            out[(co + 1) * UV2 + gy * 256 + gx + gid + 8] = v3;
        }
    }
    // reset part counters for next graph replay (last kernel in the graph)
    if (bx == 0 && by == 0 && tid < P_N) g_cnt[tid] = 0;
}

// ============================================================
// host launch
// ============================================================
#define MLP_SMEM ((48 * AST + 128 * AST) * 4 + 128 * 4 + 256)
#define WPK_TOTAL (P_N * WPK_PART)

extern "C" void kernel_launch(void* const* d_in, const int* in_sizes, int n_in,
                              void* d_out, int out_size) {
    const float* latent_z = (const float*)d_in[0];
    const float* latent_f = (const float*)d_in[1];
    const float* cano_xyz = (const float*)d_in[2];
    const float* w1in  = (const float*)d_in[3];
    const float* b1in  = (const float*)d_in[4];
    const float* w1hid = (const float*)d_in[5];
    const float* b1hid = (const float*)d_in[6];
    const float* w1out = (const float*)d_in[7];
    const float* b1out = (const float*)d_in[8];
    const float* w2in  = (const float*)d_in[9];
    const float* b2in  = (const float*)d_in[10];
    const float* w2hid = (const float*)d_in[11];
    const float* b2hid = (const float*)d_in[12];
    const float* w2out = (const float*)d_in[13];
    const float* b2out = (const float*)d_in[14];
    const float* cinw  = (const float*)d_in[15];
    const float* cinb  = (const float*)d_in[16];
    const float* chw   = (const float*)d_in[17];
    const float* chb   = (const float*)d_in[18];
    const float* cow   = (const float*)d_in[19];
    const float* cobb  = (const float*)d_in[20];
    const int* gs_part = (const int*)d_in[21];
    const int* uv_idx  = (const int*)d_in[22];
    float* out = (float*)d_out;

    cudaFuncSetAttribute(mlp_kernel, cudaFuncAttributeMaxDynamicSharedMemorySize, MLP_SMEM);

    float *uvmap, *buf0, *buf1, *wT;
    cudaGetSymbolAddress((void**)&uvmap, g_uvmap);
    cudaGetSymbolAddress((void**)&buf0, g_buf0);
    cudaGetSymbolAddress((void**)&buf1, g_buf1);
    cudaGetSymbolAddress((void**)&wT, g_wT);

    clearcount_kernel<<<2048, 256>>>(gs_part);                                 // 1
    partbias_offsets_pack_kernel<<<6 + (WPK_TOTAL + 127) / 128, 128>>>(        // 2
        latent_f, w1in, b1in, w2in, b2in, w1hid, w2hid, w1out, w2out);
    scatter_kernel<<<(G_N + 255) / 256, 256>>>(gs_part);                       // 3
    mlp_kernel<<<G_N / 64 + P_N, 256, MLP_SMEM>>>(latent_z, cano_xyz,          // 4 (capture)
        b1hid, b1out, b2hid, b2out, uv_idx);

    transpose_w_kernel<<<(WT_IN_SZ + 3 * WT_HID_SZ + WT_OUT_SZ + 255) / 256, 256>>>(cinw, chw, cow);

    dim3 cgrid(UVN / 16, UVN / 16);
    conv3x3_tf32_kernel<<<cgrid, 256>>>(uvmap, HD, wT, cinb, buf0, 0, 0);
    conv3x3_tf32_kernel<<<cgrid, 256>>>(buf0, CC, wT + WT_IN_SZ, chb, buf1, 1, 1);
    finalize_stats_kernel<<<1, 64>>>();
    conv3x3_tf32_kernel<<<cgrid, 256>>>(buf1, CC, wT + WT_IN_SZ + WT_HID_SZ, chb + CC, buf0, 2, 1);
    finalize_stats_kernel<<<1, 64>>>();
    conv3x3_tf32_kernel<<<cgrid, 256>>>(buf0, CC, wT + WT_IN_SZ + 2 * WT_HID_SZ, chb + 2 * CC, buf1, 2, 1);
    finalize_stats_kernel<<<1, 64>>>();
    convout_tf32_kernel<<<cgrid, 256>>>(buf1, cobb, out);
}